// round 17
// baseline (speedup 1.0000x reference)
#include <cuda_runtime.h>

#define T_STEPS 4096
#define NCTA    128
#define NTHR    512

typedef unsigned long long ull;

// ---------------- global scratch (static; no allocs) ----------------
// h layout: [slot][mpair 0..127][b 0..63][2] -> element (m,b) at [m>>1][b][m&1]
__device__ __align__(256) float g_h0[4][128][64][2];     // ring: h0(t) at slot t&3; slot 3 zero
__device__ __align__(256) float g_h1[4098][128][64][2];  // h1(t) at slot t+2; slots 0,1 zero
__device__ __align__(256) float g_yT[4099][64];          // yT[t+3][b] = y[b][t]; rows 0..2 pad
__device__ __align__(256) unsigned g_aflA[NCTA];  // stage-A flags; 0 between runs
__device__ __align__(256) unsigned g_aflB[NCTA];  // stage-B flags; 0 between runs
__device__ unsigned g_cnt;    // legacy barrier; 0 between runs
__device__ unsigned g_sense;  // legacy barrier; 2 teardown rounds -> returns to 0

// ---------------- helpers ----------------
__device__ __forceinline__ ull ffma2(ull h, ull w, ull a) {
    ull d;
    asm("fma.rn.f32x2 %0, %1, %2, %3;" : "=l"(d) : "l"(h), "l"(w), "l"(a));
    return d;
}
__device__ __forceinline__ float collapse2(ull a) {   // even-m sum + odd-m sum
    return __uint_as_float((unsigned)a) + __uint_as_float((unsigned)(a >> 32));
}
__device__ __forceinline__ float sigf(float x)   { return 1.0f / (1.0f + __expf(-x)); }
__device__ __forceinline__ float tanh_f(float x) { return 2.0f * sigf(2.0f * x) - 1.0f; }

__device__ __forceinline__ ulonglong2 ldcg2(const float* p) {
    ulonglong2 v;
    asm volatile("ld.global.cg.v2.u64 {%0,%1}, [%2];" : "=l"(v.x), "=l"(v.y) : "l"(p));
    return v;
}
__device__ __forceinline__ unsigned atom_add_acqrel(unsigned* p, unsigned v) {
    unsigned old;
    asm volatile("atom.acq_rel.gpu.global.add.u32 %0, [%1], %2;"
                 : "=r"(old) : "l"(p), "r"(v) : "memory");
    return old;
}
__device__ __forceinline__ unsigned ld_acquire(const unsigned* p) {
    unsigned v;
    asm volatile("ld.acquire.gpu.global.u32 %0, [%1];" : "=r"(v) : "l"(p) : "memory");
    return v;
}
__device__ __forceinline__ uint4 ld_relaxed_v4(const unsigned* p) {
    uint4 v;
    asm volatile("ld.relaxed.gpu.global.v4.u32 {%0,%1,%2,%3}, [%4];"
                 : "=r"(v.x), "=r"(v.y), "=r"(v.z), "=r"(v.w) : "l"(p) : "memory");
    return v;
}
__device__ __forceinline__ void st_release(unsigned* p, unsigned v) {
    asm volatile("st.release.gpu.global.u32 [%0], %1;" :: "l"(p), "r"(v) : "memory");
}
__device__ __forceinline__ void st_relaxed(unsigned* p, unsigned v) {
    asm volatile("st.relaxed.gpu.global.u32 [%0], %1;" :: "l"(p), "r"(v) : "memory");
}
__device__ __forceinline__ void fence_acqrel_gpu() {
    asm volatile("fence.acq_rel.gpu;" ::: "memory");
}

// wait: all flagsA >= ra AND all flagsB >= rb (direct aggregation, one warp)
__device__ __forceinline__ void wait_AB(int tid, unsigned ra, unsigned rb) {
    if (tid < 32) {
        const unsigned* fa = g_aflA + tid * 4;
        const unsigned* fb = g_aflB + tid * 4;
        for (;;) {
            uint4 a = ld_relaxed_v4(fa);
            uint4 b = ld_relaxed_v4(fb);
            bool ok = (a.x >= ra) & (a.y >= ra) & (a.z >= ra) & (a.w >= ra) &
                      (b.x >= rb) & (b.y >= rb) & (b.z >= rb) & (b.w >= rb);
            if (__all_sync(0xffffffffu, ok)) break;
        }
        fence_acqrel_gpu();
    }
    __syncthreads();
}
// wait: all flagsB >= rb
__device__ __forceinline__ void wait_B(int tid, unsigned rb) {
    if (tid < 32) {
        const unsigned* fb = g_aflB + tid * 4;
        for (;;) {
            uint4 b = ld_relaxed_v4(fb);
            if (__all_sync(0xffffffffu,
                (b.x >= rb) & (b.y >= rb) & (b.z >= rb) & (b.w >= rb))) break;
        }
        fence_acqrel_gpu();
    }
    __syncthreads();
}

// legacy atomic barrier — used exactly twice at teardown (resets itself)
__device__ __forceinline__ void grid_barrier(int tid, unsigned& ls) {
    __syncthreads();
    ls ^= 1u;
    if (tid == 0) {
        unsigned old = atom_add_acqrel(&g_cnt, 1u);
        if (old == NCTA - 1u) {
            st_relaxed(&g_cnt, 0u);
            st_release(&g_sense, ls);
        } else {
            while (ld_acquire(&g_sense) != ls) { }
        }
    }
    __syncthreads();
}

// ---------------- smem layout (floats) ----------------
//   W0s [8][256]    @ 0      (2048)  W_hh0 rows, plain fp32 K-major
//   W1s [8][256]    @ 2048   (2048)  W_ih1
//   WHs [8][256]    @ 4096   (2048)  W_hh1
//   P0  [16][8][64] @ 6144   (8192)  layer0 gate partials (q, row, batch)
//   P1  [16][8][64] @ 14336  (8192)
//   misc @ 22528: wih0[8][4]=32, b0s[8], b1s[8], yw[4][64]=256, wout[512], bo2[2]
#define SMEM_FLOATS (22528 + 818)
#define SMEM_BYTES  (SMEM_FLOATS * 4)

__global__ void __launch_bounds__(NTHR, 1) lstm_all(
    const float* __restrict__ y,
    const float* __restrict__ Wih0, const float* __restrict__ Whh0,
    const float* __restrict__ bih0, const float* __restrict__ bhh0,
    const float* __restrict__ Wih1, const float* __restrict__ Whh1,
    const float* __restrict__ bih1, const float* __restrict__ bhh1,
    const float* __restrict__ Wout, const float* __restrict__ bout,
    float* __restrict__ out)
{
    extern __shared__ float sm[];
    float* W0s  = sm;              // [8][256]
    float* W1s  = sm + 2048;       // [8][256]
    float* WHs  = sm + 4096;       // [8][256]
    float* P0   = sm + 6144;       // [16][8][64]
    float* P1   = sm + 14336;      // [16][8][64]
    float* wih0 = sm + 22528;      // [8][4]
    float* b0s  = wih0 + 32;       // [8]
    float* b1s  = b0s + 8;         // [8]
    float* yw   = b1s + 8;         // [4][64]
    float* wout = yw + 256;        // [2][256]
    float* bo2  = wout + 512;      // [2]

    const int tid = threadIdx.x;
    const int bid = blockIdx.x;
    const int j0  = bid * 2;                 // CTA owns hidden units j0, j0+1
    unsigned ls = 0;

    // ======== init: global state ========
    {
        int gi = bid * NTHR + tid;           // 0..65535
        if (gi < 16384) ((float*)g_h0)[3 * 16384 + gi] = 0.0f;  // ring slot 3 = h0(-1)
        if (gi < 32768) ((float*)g_h1)[gi] = 0.0f;              // h1 slots 0,1
        for (int i = gi; i < 4099 * 64; i += NCTA * NTHR) {
            int row = i >> 6, b = i & 63;
            g_yT[row][b] = (row < 3) ? -100.0f : y[b * T_STEPS + (row - 3)];
        }
    }

    // ======== init: smem weights (plain fp32 rows; r = gate*2 + lj) ========
    for (int idx = tid; idx < 8 * 256; idx += NTHR) {
        int r = idx >> 8, m = idx & 255;
        int row = (r >> 1) * 256 + j0 + (r & 1);
        W0s[idx] = Whh0[row * 256 + m];
        W1s[idx] = Wih1[row * 256 + m];
        WHs[idx] = Whh1[row * 256 + m];
    }
    if (tid < 8) {
        int row = (tid >> 1) * 256 + j0 + (tid & 1);
        b0s[tid] = bih0[row] + bhh0[row];
        b1s[tid] = bih1[row] + bhh1[row];
        for (int k = 0; k < 4; k++) wih0[tid * 4 + k] = Wih0[row * 4 + k];
    }
    wout[tid & 511] = Wout[tid & 511];
    if (tid < 2) bo2[tid] = bout[tid];
    __syncthreads();
    if (tid == 0) {
        __threadfence();
        st_release(&g_aflA[bid], 1u);
        st_release(&g_aflB[bid], 1u);
    }

    // ======== persistent 2-layer LSTM (layer1 lags 2 steps) ========
    const int q    = tid >> 5;               // warp id = m-chunk (16 m per chunk)
    const int lane = tid & 31;                // batch pair: batches 2*lane, 2*lane+1
    const float* W0r = W0s + q * 16;          // + r*256 + mp2*4
    const float* W1r = W1s + q * 16;
    const float* WHr = WHs + q * 16;
    const int hfl = q * 8 * 128 + 4 * lane;   // float offset of thread's first K-pair

    // cell roles (tid < 128): both layers' cells live on the same threads
    const int clb = tid & 63;
    const int clj = (tid >> 6) & 1;
    float c0reg = 0.0f, c1reg = 0.0f;

    for (int p = 0; p <= T_STEPS + 1; p++) {
        // ---- phase-start wait: h0(p-1) ready (A), ring-WAR cover (B >= p) ----
        wait_AB(tid, (unsigned)(p + 1), (unsigned)(p > 1 ? p : 1));

        // ================= STAGE A : layer0 step p =================
        const float* H0 = &g_h0[(p + 3) & 3][0][0][0] + hfl;   // h0(p-1)
        if (tid < 256 && p < T_STEPS) yw[tid] = g_yT[p + (tid >> 6)][tid & 63];

        ulonglong2 h0r[8];
        #pragma unroll
        for (int i = 0; i < 8; i++) h0r[i] = ldcg2(H0 + i * 128);

        {
            ull aA[8], aB[8];
            #pragma unroll
            for (int r = 0; r < 8; r++) { aA[r] = 0ull; aB[r] = 0ull; }
            #pragma unroll
            for (int mp2 = 0; mp2 < 4; mp2++) {
                const ulonglong2 hE = h0r[2 * mp2], hO = h0r[2 * mp2 + 1];
                #pragma unroll
                for (int r = 0; r < 8; r++) {
                    ulonglong2 wv = *(const ulonglong2*)(W0r + r * 256 + mp2 * 4);
                    aA[r] = ffma2(hE.x, wv.x, aA[r]);
                    aB[r] = ffma2(hE.y, wv.x, aB[r]);
                    aA[r] = ffma2(hO.x, wv.y, aA[r]);
                    aB[r] = ffma2(hO.y, wv.y, aB[r]);
                }
            }
            #pragma unroll
            for (int r = 0; r < 8; r++) {
                float2 v = make_float2(collapse2(aA[r]), collapse2(aB[r]));
                *(float2*)(P0 + q * 512 + r * 64 + 2 * lane) = v;
            }
        }
        __syncthreads();

        if (tid < 128 && p < T_STEPS) {       // reduce + cell0 + publish h0(p)
            float gg[4];
            #pragma unroll
            for (int gt = 0; gt < 4; gt++) {
                int r = gt * 2 + clj;
                float s = b0s[r];
                #pragma unroll
                for (int qq = 0; qq < 16; qq++)
                    s += P0[qq * 512 + r * 64 + clb];
                #pragma unroll
                for (int k = 0; k < 4; k++)
                    s = fmaf(yw[k * 64 + clb], wih0[r * 4 + k], s);
                gg[gt] = s;
            }
            c0reg = sigf(gg[1]) * c0reg + sigf(gg[0]) * tanh_f(gg[2]);
            float h = sigf(gg[3]) * tanh_f(c0reg);
            int j = j0 + clj;
            g_h0[p & 3][j >> 1][clb][j & 1] = h;      // h0(p)
        }
        __syncthreads();
        if (tid == 0) st_release(&g_aflA[bid], (unsigned)(p + 2));   // h0(p) visible

        // ================= STAGE B : layer1 step p-2 =================
        // ih-half first (h0(p-2) is gated by the A-wait above) to hide wait_B
        const float* H0o = &g_h0[(p + 2) & 3][0][0][0] + hfl;  // h0(p-2)
        ull aA[8], aB[8];
        #pragma unroll
        for (int r = 0; r < 8; r++) { aA[r] = 0ull; aB[r] = 0ull; }
        {
            ulonglong2 h0o[8];
            #pragma unroll
            for (int i = 0; i < 8; i++) h0o[i] = ldcg2(H0o + i * 128);
            #pragma unroll
            for (int mp2 = 0; mp2 < 4; mp2++) {
                const ulonglong2 hE = h0o[2 * mp2], hO = h0o[2 * mp2 + 1];
                #pragma unroll
                for (int r = 0; r < 8; r++) {
                    ulonglong2 wv = *(const ulonglong2*)(W1r + r * 256 + mp2 * 4);
                    aA[r] = ffma2(hE.x, wv.x, aA[r]);
                    aB[r] = ffma2(hE.y, wv.x, aB[r]);
                    aA[r] = ffma2(hO.x, wv.y, aA[r]);
                    aB[r] = ffma2(hO.y, wv.y, aB[r]);
                }
            }
        }

        wait_B(tid, (unsigned)(p + 1));        // h1(p-3) ready (end of phase p-1)

        {
            const float* H1 = &g_h1[(p >= 1 ? p - 1 : 0)][0][0][0] + hfl;  // h1(p-3)
            ulonglong2 h1r[8];
            #pragma unroll
            for (int i = 0; i < 8; i++) h1r[i] = ldcg2(H1 + i * 128);
            #pragma unroll
            for (int mp2 = 0; mp2 < 4; mp2++) {
                const ulonglong2 hE = h1r[2 * mp2], hO = h1r[2 * mp2 + 1];
                #pragma unroll
                for (int r = 0; r < 8; r++) {
                    ulonglong2 wv = *(const ulonglong2*)(WHr + r * 256 + mp2 * 4);
                    aA[r] = ffma2(hE.x, wv.x, aA[r]);
                    aB[r] = ffma2(hE.y, wv.x, aB[r]);
                    aA[r] = ffma2(hO.x, wv.y, aA[r]);
                    aB[r] = ffma2(hO.y, wv.y, aB[r]);
                }
            }
            #pragma unroll
            for (int r = 0; r < 8; r++) {
                float2 v = make_float2(collapse2(aA[r]), collapse2(aB[r]));
                *(float2*)(P1 + q * 512 + r * 64 + 2 * lane) = v;
            }
        }
        __syncthreads();

        if (tid < 128 && p >= 2) {             // reduce + cell1 + publish h1(p-2)
            float gg[4];
            #pragma unroll
            for (int gt = 0; gt < 4; gt++) {
                int r = gt * 2 + clj;
                float s = b1s[r];
                #pragma unroll
                for (int qq = 0; qq < 16; qq++)
                    s += P1[qq * 512 + r * 64 + clb];
                gg[gt] = s;
            }
            c1reg = sigf(gg[1]) * c1reg + sigf(gg[0]) * tanh_f(gg[2]);
            float h = sigf(gg[3]) * tanh_f(c1reg);
            int j = j0 + clj;
            g_h1[p][j >> 1][clb][j & 1] = h;          // h1(p-2) at slot (p-2)+2
        }
        __syncthreads();
        if (tid == 0) st_release(&g_aflB[bid], (unsigned)(p + 2));
    }

    // ======== teardown: reset flag state, legacy barriers return to 0 ========
    grid_barrier(tid, ls);                       // everyone past final flag use
    if (tid == 0) {
        st_relaxed(&g_aflA[bid], 0u);
        st_relaxed(&g_aflB[bid], 0u);
    }
    grid_barrier(tid, ls);                       // 2 rounds -> g_sense back to 0

    // ======== output projection: out[b][t][k] = h1(t).Wout[k] + bout[k] ========
    {
        const int b  = tid & 63;
        const int tt = tid >> 6;    // 0..7
        #pragma unroll
        for (int u = 0; u < 4; u++) {
            int t = bid * 32 + tt * 4 + u;
            const float* h = &g_h1[t + 2][0][0][0] + b * 2;
            float s0 = bo2[0], s1 = bo2[1];
            #pragma unroll 8
            for (int mp = 0; mp < 128; mp++) {
                float2 v = *(const float2*)(h + mp * 128);
                s0 = fmaf(v.x, wout[2 * mp],       s0);
                s0 = fmaf(v.y, wout[2 * mp + 1],   s0);
                s1 = fmaf(v.x, wout[256 + 2 * mp], s1);
                s1 = fmaf(v.y, wout[257 + 2 * mp], s1);
            }
            out[b * (T_STEPS * 2) + t * 2 + 0] = s0;
            out[b * (T_STEPS * 2) + t * 2 + 1] = s1;
        }
    }
}

// ---------------- launcher: ONE kernel ----------------
extern "C" void kernel_launch(void* const* d_in, const int* in_sizes, int n_in,
                              void* d_out, int out_size)
{
    (void)in_sizes; (void)n_in; (void)out_size;
    cudaFuncSetAttribute(lstm_all, cudaFuncAttributeMaxDynamicSharedMemorySize, SMEM_BYTES);
    lstm_all<<<NCTA, NTHR, SMEM_BYTES>>>(
        (const float*)d_in[0],
        (const float*)d_in[1], (const float*)d_in[2],
        (const float*)d_in[3], (const float*)d_in[4],
        (const float*)d_in[5], (const float*)d_in[6],
        (const float*)d_in[7], (const float*)d_in[8],
        (const float*)d_in[9], (const float*)d_in[10],
        (float*)d_out);
}